// round 6
// baseline (speedup 1.0000x reference)
#include <cuda_runtime.h>

// LatticeSnake: B=16, N=48, K=7, PAD=3. Reference scatters 48 acids + 47
// inters into a 195^3 lattice (in-order, last-write-wins), extracts a 7^3
// window at each acid's idx2, masks by mask[n].
//
// R6: same scatter design (candidate x window all-pairs; packed
// (cand_index+1)<<32 | float_bits atomicMax == in-order last-write-wins).
// Floor-tuned: WPC=4 -> grid 12x16=192 CTAs, 256 threads (shorter barrier /
// arbiter tail), float2-vectorized final store. Kernel is launch-latency
// bound (all pipes <5% in R3-R5); this trims the CTA drain term only.
//
// mask is int32 (harness materializes JAX bool as 4-byte ints).

#define NACID   48
#define KWIN    7
#define PADW    3
#define CELLS   (KWIN * KWIN * KWIN)   // 343
#define NCAND   (2 * NACID - 1)        // 95
#define WPC     4                      // windows per CTA
#define SLICES  (NACID / WPC)          // 12
#define NTHREADS 256

__global__ __launch_bounds__(NTHREADS)
void lattice_snake_kernel(const float* __restrict__ acids,
                          const int* __restrict__ mask,
                          const int* __restrict__ idx,
                          float* __restrict__ out)
{
    __shared__ __align__(16) unsigned long long buf[WPC * CELLS]; // (i+1)<<32 | valbits
    __shared__ int4  cand[NCAND];                                 // cx, cy, cz, value bits
    __shared__ int   wbase[WPC][3];
    __shared__ float wmask[WPC];

    const int slice = blockIdx.x;      // 0..11
    const int b     = blockIdx.y;      // 0..15
    const int t     = threadIdx.x;

    const int*   idxb = idx   + b * NACID * 3;
    const float* ab   = acids + b * NACID;
    const int*   mb   = mask  + b * NACID;

    // ---- stage 1: zero buffer (u64x2), build candidates, window bases ----
    {
        ulonglong2* bz = (ulonglong2*)buf;
        #pragma unroll
        for (int c = t; c < (WPC * CELLS) / 2; c += NTHREADS)
            bz[c] = make_ulonglong2(0ULL, 0ULL);
    }

    if (t < NCAND) {
        int cx, cy, cz, live;
        float v;
        if (t < NACID) {
            cx = 2 * idxb[3 * t + 0] + 94 + PADW;
            cy = 2 * idxb[3 * t + 1] + 94 + PADW;
            cz = 2 * idxb[3 * t + 2] + 94 + PADW;
            live = mb[t];
            v = ab[t];
        } else {
            const int j = t - NACID;   // 0..46
            cx = idxb[3 * j + 0] + idxb[3 * (j + 1) + 0] + 94 + PADW;
            cy = idxb[3 * j + 1] + idxb[3 * (j + 1) + 1] + 94 + PADW;
            cz = idxb[3 * j + 2] + idxb[3 * (j + 1) + 2] + 94 + PADW;
            live = mb[j + 1];
            v = ab[j] + ab[j + 1] + 1.0f;
        }
        if (!live) cx = 1 << 20;       // out of unsigned<7 range -> never hits
        cand[t] = make_int4(cx, cy, cz, __float_as_int(v));
    } else if (t >= 128 && t < 128 + WPC) {
        const int w = t - 128;
        const int n = slice * WPC + w;
        wbase[w][0] = 2 * idxb[3 * n + 0] + 94;
        wbase[w][1] = 2 * idxb[3 * n + 1] + 94;
        wbase[w][2] = 2 * idxb[3 * n + 2] + 94;
        wmask[w] = mb[n] ? 1.0f : 0.0f;
    }
    __syncthreads();

    // ---- stage 2: all-pairs candidate x window scatter (380 pairs) ----
    #pragma unroll
    for (int p = t; p < WPC * NCAND; p += NTHREADS) {
        const int w = p / NCAND;
        const int i = p - w * NCAND;
        const int4 c = cand[i];
        const int dx = c.x - wbase[w][0];
        const int dy = c.y - wbase[w][1];
        const int dz = c.z - wbase[w][2];
        if ((unsigned)dx < KWIN && (unsigned)dy < KWIN && (unsigned)dz < KWIN) {
            const unsigned long long pk =
                ((unsigned long long)(i + 1) << 32) | (unsigned)c.w;
            atomicMax(&buf[w * CELLS + dx * 49 + dy * 7 + dz], pk);
        }
    }
    __syncthreads();

    // ---- stage 3: float2-vectorized contiguous store (1372 floats = 686 f2) ----
    float2* outb = (float2*)(out + (b * NACID + slice * WPC) * CELLS);
    #pragma unroll
    for (int c2 = t; c2 < (WPC * CELLS) / 2; c2 += NTHREADS) {
        const int c = 2 * c2;
        const int w0 = c / CELLS;
        const int w1 = (c + 1) / CELLS;
        const unsigned long long p0 = buf[c];
        const unsigned long long p1 = buf[c + 1];
        float2 v;
        v.x = (p0 >> 32) ? __int_as_float((int)(unsigned)p0) * wmask[w0] : 0.0f;
        v.y = (p1 >> 32) ? __int_as_float((int)(unsigned)p1) * wmask[w1] : 0.0f;
        outb[c2] = v;
    }
}

extern "C" void kernel_launch(void* const* d_in, const int* in_sizes, int n_in,
                              void* d_out, int out_size)
{
    const float* acids = (const float*)d_in[0];   // (B, N) float32
    const int*   mask  = (const int*)d_in[1];     // (B, N) bool -> int32
    const int*   idx   = (const int*)d_in[2];     // (B, N, 3) int32
    float*       out   = (float*)d_out;           // (B, N, 7,7,7, 1) float32

    dim3 grid(SLICES, 16);
    lattice_snake_kernel<<<grid, NTHREADS>>>(acids, mask, idx, out);
}